// round 1
// baseline (speedup 1.0000x reference)
#include <cuda_runtime.h>
#include <cstdint>

#define NN 50000
#define EE 800000
#define HIDC 128
#define OUTC 64
#define EPSF 1e-5f

// ---------------- scratch (device globals; no allocation allowed) ----------------
__device__ float g_deg[NN];
__device__ float g_dinv[NN];
__device__ float g_tx1[(size_t)NN * HIDC];
__device__ float g_h[(size_t)NN * HIDC];
__device__ float g_th[(size_t)NN * HIDC];
__device__ float g_sum[HIDC];
__device__ float g_sumsq[HIDC];
__device__ float g_scale[HIDC];
__device__ float g_shift[HIDC];

// ---------------- zero everything we accumulate into ----------------
__global__ void k_zero() {
    size_t stride = (size_t)gridDim.x * blockDim.x;
    size_t total = (size_t)NN * HIDC;
    for (size_t j = (size_t)blockIdx.x * blockDim.x + threadIdx.x; j < total; j += stride) {
        g_tx1[j] = 0.f;
        g_th[j] = 0.f;
        if (j < NN) g_deg[j] = 0.f;
        if (j < HIDC) { g_sum[j] = 0.f; g_sumsq[j] = 0.f; }
    }
}

// ---------------- degree over src ----------------
__global__ void k_deg(const int* __restrict__ src) {
    int e = blockIdx.x * blockDim.x + threadIdx.x;
    if (e < EE) atomicAdd(&g_deg[src[e]], 1.0f);
}

__global__ void k_dinv() {
    int i = blockIdx.x * blockDim.x + threadIdx.x;
    if (i < NN) {
        float d = g_deg[i];
        g_dinv[i] = (d > 0.5f) ? rsqrtf(d) : 0.f;
    }
}

// ---------------- scatter: out[dst] += norm * X[src], 128 wide; one warp per edge ----------------
__global__ void k_scatter(const int* __restrict__ src, const int* __restrict__ dst,
                          const float* __restrict__ Xin, int phase) {
    size_t gtid = (size_t)blockIdx.x * blockDim.x + threadIdx.x;
    int e = (int)(gtid >> 5);
    if (e >= EE) return;
    int lane = threadIdx.x & 31;
    const float* X = phase ? g_h : Xin;
    float* O = phase ? g_th : g_tx1;
    int s = src[e], d = dst[e];
    float nrm = -g_dinv[s] * g_dinv[d];
    float4 v = ((const float4*)(X + (size_t)s * HIDC))[lane];
    v.x *= nrm; v.y *= nrm; v.z *= nrm; v.w *= nrm;
    float* o = O + (size_t)d * HIDC + lane * 4;
    asm volatile("red.global.add.v4.f32 [%0], {%1,%2,%3,%4};"
                 :: "l"(o), "f"(v.x), "f"(v.y), "f"(v.z), "f"(v.w) : "memory");
}

// ---------------- GEMM1: g_h = X @ W0 + g_tx1 @ W1 + b ----------------
// block: 256 threads, tile 64 rows x 128 cols, thread tile 4x8, weights in smem
__global__ void k_gemm1(const float* __restrict__ X, const float* __restrict__ W0,
                        const float* __restrict__ W1, const float* __restrict__ bias) {
    extern __shared__ float sm[];
    float* W0s = sm;                  // 128*128
    float* W1s = sm + 16384;          // 128*128
    float* xs  = sm + 32768;          // 64*128
    float* ts  = sm + 40960;          // 64*128
    int t = threadIdx.x;
    int row0 = blockIdx.x * 64;

    for (int i = t; i < 4096; i += 256) {
        ((float4*)W0s)[i] = ((const float4*)W0)[i];
        ((float4*)W1s)[i] = ((const float4*)W1)[i];
    }
    for (int i = t; i < 2048; i += 256) {
        int r = i >> 5, c4 = i & 31;
        int row = row0 + r;
        float4 vx = make_float4(0.f, 0.f, 0.f, 0.f), vt = vx;
        if (row < NN) {
            vx = ((const float4*)(X + (size_t)row * HIDC))[c4];
            vt = ((const float4*)(g_tx1 + (size_t)row * HIDC))[c4];
        }
        ((float4*)xs)[i] = vx;
        ((float4*)ts)[i] = vt;
    }
    __syncthreads();

    int tx = t & 15, ty = t >> 4;
    int cb = tx * 8, rb = ty * 4;
    float acc[4][8];
#pragma unroll
    for (int r = 0; r < 4; r++)
#pragma unroll
        for (int j = 0; j < 8; j++) acc[r][j] = 0.f;

#pragma unroll 2
    for (int k = 0; k < HIDC; k++) {
        float a[4], b[4];
#pragma unroll
        for (int r = 0; r < 4; r++) {
            a[r] = xs[(rb + r) * HIDC + k];
            b[r] = ts[(rb + r) * HIDC + k];
        }
        float4 w0a = *(float4*)&W0s[k * HIDC + cb];
        float4 w0b = *(float4*)&W0s[k * HIDC + cb + 4];
        float4 w1a = *(float4*)&W1s[k * HIDC + cb];
        float4 w1b = *(float4*)&W1s[k * HIDC + cb + 4];
        float w0[8] = {w0a.x, w0a.y, w0a.z, w0a.w, w0b.x, w0b.y, w0b.z, w0b.w};
        float w1[8] = {w1a.x, w1a.y, w1a.z, w1a.w, w1b.x, w1b.y, w1b.z, w1b.w};
#pragma unroll
        for (int r = 0; r < 4; r++)
#pragma unroll
            for (int j = 0; j < 8; j++)
                acc[r][j] += a[r] * w0[j] + b[r] * w1[j];
    }

    float bb[8];
#pragma unroll
    for (int j = 0; j < 8; j++) bb[j] = bias[cb + j];
#pragma unroll
    for (int r = 0; r < 4; r++) {
        int row = row0 + rb + r;
        if (row < NN) {
            float4 o1 = make_float4(acc[r][0] + bb[0], acc[r][1] + bb[1],
                                    acc[r][2] + bb[2], acc[r][3] + bb[3]);
            float4 o2 = make_float4(acc[r][4] + bb[4], acc[r][5] + bb[5],
                                    acc[r][6] + bb[6], acc[r][7] + bb[7]);
            float4* op = (float4*)(g_h + (size_t)row * HIDC + cb);
            op[0] = o1;
            op[1] = o2;
        }
    }
}

// ---------------- BN column sums ----------------
__global__ void k_colsum() {
    __shared__ float s1[256], s2[256];
    int t = threadIdx.x;
    int c = t & 127, half = t >> 7;
    float s = 0.f, q = 0.f;
    for (int r = blockIdx.x * 2 + half; r < NN; r += gridDim.x * 2) {
        float v = g_h[(size_t)r * HIDC + c];
        s += v;
        q += v * v;
    }
    s1[t] = s;
    s2[t] = q;
    __syncthreads();
    if (half == 0) {
        atomicAdd(&g_sum[c], s1[t] + s1[t + 128]);
        atomicAdd(&g_sumsq[c], s2[t] + s2[t + 128]);
    }
}

__global__ void k_stats(const float* __restrict__ gamma, const float* __restrict__ beta) {
    int c = threadIdx.x;
    if (c < HIDC) {
        float mean = g_sum[c] * (1.0f / NN);
        float var = fmaxf(g_sumsq[c] * (1.0f / NN) - mean * mean, 0.f);
        float sc = gamma[c] * rsqrtf(var + EPSF);
        g_scale[c] = sc;
        g_shift[c] = beta[c] - mean * sc;
    }
}

__global__ void k_bnrelu() {
    size_t total = (size_t)NN * (HIDC / 4);
    size_t stride = (size_t)gridDim.x * blockDim.x;
    for (size_t i = (size_t)blockIdx.x * blockDim.x + threadIdx.x; i < total; i += stride) {
        int c4 = (int)(i & 31);
        float4 v = ((float4*)g_h)[i];
        float4 sc = ((const float4*)g_scale)[c4];
        float4 sh = ((const float4*)g_shift)[c4];
        v.x = fmaxf(fmaf(v.x, sc.x, sh.x), 0.f);
        v.y = fmaxf(fmaf(v.y, sc.y, sh.y), 0.f);
        v.z = fmaxf(fmaf(v.z, sc.z, sh.z), 0.f);
        v.w = fmaxf(fmaf(v.w, sc.w, sh.w), 0.f);
        ((float4*)g_h)[i] = v;
    }
}

// ---------------- GEMM2: mu = h@Wmu0 + th@Wmu1 + bmu ; ls = h@Wls0 + th@Wls1 + bls ----------------
// Same structure as GEMM1; 128 output cols = [mu(64) | ls(64)] packed side-by-side in smem weights.
__global__ void k_gemm2(const float* __restrict__ Wmu0, const float* __restrict__ Wmu1,
                        const float* __restrict__ Wls0, const float* __restrict__ Wls1,
                        const float* __restrict__ bmu, const float* __restrict__ bls,
                        float* __restrict__ out) {
    extern __shared__ float sm[];
    float* W0s = sm;
    float* W1s = sm + 16384;
    float* xs  = sm + 32768;
    float* ts  = sm + 40960;
    int t = threadIdx.x;
    int row0 = blockIdx.x * 64;

    for (int i = t; i < 4096; i += 256) {
        int k = i >> 5, c4 = i & 31;
        float4 v0, v1;
        if (c4 < 16) {
            v0 = ((const float4*)(Wmu0 + (size_t)k * OUTC))[c4];
            v1 = ((const float4*)(Wmu1 + (size_t)k * OUTC))[c4];
        } else {
            v0 = ((const float4*)(Wls0 + (size_t)k * OUTC))[c4 - 16];
            v1 = ((const float4*)(Wls1 + (size_t)k * OUTC))[c4 - 16];
        }
        ((float4*)W0s)[i] = v0;
        ((float4*)W1s)[i] = v1;
    }
    for (int i = t; i < 2048; i += 256) {
        int r = i >> 5, c4 = i & 31;
        int row = row0 + r;
        float4 vx = make_float4(0.f, 0.f, 0.f, 0.f), vt = vx;
        if (row < NN) {
            vx = ((const float4*)(g_h + (size_t)row * HIDC))[c4];
            vt = ((const float4*)(g_th + (size_t)row * HIDC))[c4];
        }
        ((float4*)xs)[i] = vx;
        ((float4*)ts)[i] = vt;
    }
    __syncthreads();

    int tx = t & 15, ty = t >> 4;
    int cb = tx * 8, rb = ty * 4;
    float acc[4][8];
#pragma unroll
    for (int r = 0; r < 4; r++)
#pragma unroll
        for (int j = 0; j < 8; j++) acc[r][j] = 0.f;

#pragma unroll 2
    for (int k = 0; k < HIDC; k++) {
        float a[4], b[4];
#pragma unroll
        for (int r = 0; r < 4; r++) {
            a[r] = xs[(rb + r) * HIDC + k];
            b[r] = ts[(rb + r) * HIDC + k];
        }
        float4 w0a = *(float4*)&W0s[k * HIDC + cb];
        float4 w0b = *(float4*)&W0s[k * HIDC + cb + 4];
        float4 w1a = *(float4*)&W1s[k * HIDC + cb];
        float4 w1b = *(float4*)&W1s[k * HIDC + cb + 4];
        float w0[8] = {w0a.x, w0a.y, w0a.z, w0a.w, w0b.x, w0b.y, w0b.z, w0b.w};
        float w1[8] = {w1a.x, w1a.y, w1a.z, w1a.w, w1b.x, w1b.y, w1b.z, w1b.w};
#pragma unroll
        for (int r = 0; r < 4; r++)
#pragma unroll
            for (int j = 0; j < 8; j++)
                acc[r][j] += a[r] * w0[j] + b[r] * w1[j];
    }

    bool isMu = (tx < 8);
    int colLocal = isMu ? cb : (cb - 64);
    const float* bp = isMu ? bmu : bls;
    size_t obase = isMu ? 0 : (size_t)NN * OUTC;
    float bb[8];
#pragma unroll
    for (int j = 0; j < 8; j++) bb[j] = bp[colLocal + j];
#pragma unroll
    for (int r = 0; r < 4; r++) {
        int row = row0 + rb + r;
        if (row < NN) {
            float4 o1 = make_float4(acc[r][0] + bb[0], acc[r][1] + bb[1],
                                    acc[r][2] + bb[2], acc[r][3] + bb[3]);
            float4 o2 = make_float4(acc[r][4] + bb[4], acc[r][5] + bb[5],
                                    acc[r][6] + bb[6], acc[r][7] + bb[7]);
            float4* op = (float4*)(out + obase + (size_t)row * OUTC + colLocal);
            op[0] = o1;
            op[1] = o2;
        }
    }
}

// ---------------- launch ----------------
extern "C" void kernel_launch(void* const* d_in, const int* in_sizes, int n_in,
                              void* d_out, int out_size) {
    const float* x     = (const float*)d_in[0];
    const int*   ei    = (const int*)d_in[1];
    const int*   src   = ei;
    const int*   dst   = ei + EE;
    const float* W1_0  = (const float*)d_in[2];
    const float* W1_1  = (const float*)d_in[3];
    const float* b1    = (const float*)d_in[4];
    const float* gamma = (const float*)d_in[5];
    const float* beta  = (const float*)d_in[6];
    const float* Wmu0  = (const float*)d_in[7];
    const float* Wmu1  = (const float*)d_in[8];
    const float* bmu   = (const float*)d_in[9];
    const float* Wls0  = (const float*)d_in[10];
    const float* Wls1  = (const float*)d_in[11];
    const float* bls   = (const float*)d_in[12];
    float* out = (float*)d_out;

    cudaFuncSetAttribute(k_gemm1, cudaFuncAttributeMaxDynamicSharedMemorySize, 196608);
    cudaFuncSetAttribute(k_gemm2, cudaFuncAttributeMaxDynamicSharedMemorySize, 196608);

    k_zero<<<2048, 256>>>();
    k_deg<<<(EE + 255) / 256, 256>>>(src);
    k_dinv<<<(NN + 255) / 256, 256>>>();
    k_scatter<<<(int)(((size_t)EE * 32 + 255) / 256), 256>>>(src, dst, x, 0);
    k_gemm1<<<(NN + 63) / 64, 256, 196608>>>(x, W1_0, W1_1, b1);
    k_colsum<<<1024, 256>>>();
    k_stats<<<1, 128>>>(gamma, beta);
    k_bnrelu<<<2048, 256>>>();
    k_scatter<<<(int)(((size_t)EE * 32 + 255) / 256), 256>>>(src, dst, x, 1);
    k_gemm2<<<(NN + 63) / 64, 256, 196608>>>(Wmu0, Wmu1, Wls0, Wls1, bmu, bls, out);
}

// round 2
// speedup vs baseline: 1.3212x; 1.3212x over previous
#include <cuda_runtime.h>
#include <cstdint>

#define NN 50000
#define EE 800000
#define HIDC 128
#define OUTC 64
#define EPSF 1e-5f
#define NCHUNK 196   // ceil(NN/256)

// ---------------- scratch (device globals; no allocation allowed) ----------------
__device__ float g_deg[NN];
__device__ float g_dinv[NN];
__device__ float g_tx1[(size_t)NN * HIDC];
__device__ float g_h[(size_t)NN * HIDC];
__device__ float g_th[(size_t)NN * HIDC];
__device__ float g_sum[HIDC];
__device__ float g_sumsq[HIDC];
__device__ float g_scale[HIDC];
__device__ float g_shift[HIDC];
// CSR scratch
__device__ int   g_cnt[NN];
__device__ int   g_bsum[NCHUNK];
__device__ int   g_boff[NCHUNK];
__device__ int   g_rowptr[NN + 1];
__device__ int   g_cursor[NN];
__device__ int   g_csr_src[EE];
__device__ float g_csr_w[EE];

// ---------------- f32x2 helpers ----------------
#define FMA2(acc, a, w) \
    asm("fma.rn.f32x2 %0, %1, %2, %0;" : "+l"(acc) : "l"(a), "l"(w))
#define PACK2(d, f) \
    asm("mov.b64 %0, {%1, %1};" : "=l"(d) : "r"(__float_as_uint(f)))
#define UNPACK2(lo, hi, v) \
    asm("mov.b64 {%0, %1}, %2;" : "=f"(lo), "=f"(hi) : "l"(v))

// ---------------- small zero ----------------
__global__ void k_zero_small() {
    int i = blockIdx.x * blockDim.x + threadIdx.x;
    if (i < NN) { g_deg[i] = 0.f; g_cnt[i] = 0; }
    if (i < HIDC) { g_sum[i] = 0.f; g_sumsq[i] = 0.f; }
}

// ---------------- deg over src + in-count over dst ----------------
__global__ void k_prep(const int* __restrict__ src, const int* __restrict__ dst) {
    int e = blockIdx.x * blockDim.x + threadIdx.x;
    if (e < EE) {
        atomicAdd(&g_deg[src[e]], 1.0f);
        atomicAdd(&g_cnt[dst[e]], 1);
    }
}

__global__ void k_dinv() {
    int i = blockIdx.x * blockDim.x + threadIdx.x;
    if (i < NN) {
        float d = g_deg[i];
        g_dinv[i] = (d > 0.5f) ? rsqrtf(d) : 0.f;
    }
}

// ---------------- scan: chunk sums -> scan of sums -> per-chunk scan ----------------
__global__ void k_chunksum() {
    __shared__ int s[256];
    int c = blockIdx.x * 256 + threadIdx.x;
    s[threadIdx.x] = (c < NN) ? g_cnt[c] : 0;
    __syncthreads();
    for (int off = 128; off > 0; off >>= 1) {
        if (threadIdx.x < off) s[threadIdx.x] += s[threadIdx.x + off];
        __syncthreads();
    }
    if (threadIdx.x == 0) g_bsum[blockIdx.x] = s[0];
}

__global__ void k_bscan() {
    if (threadIdx.x == 0) {
        int acc = 0;
        for (int i = 0; i < NCHUNK; i++) { int t = g_bsum[i]; g_boff[i] = acc; acc += t; }
        g_rowptr[NN] = EE;
    }
}

__global__ void k_chunkscan() {
    __shared__ int s[256];
    int c = blockIdx.x * 256 + threadIdx.x;
    int v = (c < NN) ? g_cnt[c] : 0;
    s[threadIdx.x] = v;
    __syncthreads();
    for (int off = 1; off < 256; off <<= 1) {
        int t = (threadIdx.x >= off) ? s[threadIdx.x - off] : 0;
        __syncthreads();
        s[threadIdx.x] += t;
        __syncthreads();
    }
    if (c < NN) {
        int excl = g_boff[blockIdx.x] + s[threadIdx.x] - v;
        g_rowptr[c] = excl;
        g_cursor[c] = excl;
    }
}

__global__ void k_fill(const int* __restrict__ src, const int* __restrict__ dst) {
    int e = blockIdx.x * blockDim.x + threadIdx.x;
    if (e < EE) {
        int s = src[e], d = dst[e];
        int p = atomicAdd(&g_cursor[d], 1);
        g_csr_src[p] = s;
        g_csr_w[p] = g_dinv[s];
    }
}

// ---------------- gather 1: g_tx1[d] = sum_in-edges -dinv[s]*dinv[d] * X[s] ----------------
__global__ void k_gather1(const float* __restrict__ X) {
    int warp = (int)(((size_t)blockIdx.x * blockDim.x + threadIdx.x) >> 5);
    if (warp >= NN) return;
    int lane = threadIdx.x & 31;
    int d = warp;
    int j = g_rowptr[d], end = g_rowptr[d + 1];
    float ndd = -g_dinv[d];
    float4 acc = make_float4(0.f, 0.f, 0.f, 0.f);
    for (; j + 2 <= end; j += 2) {
        int s0 = __ldg(&g_csr_src[j]), s1 = __ldg(&g_csr_src[j + 1]);
        float w0 = ndd * __ldg(&g_csr_w[j]);
        float w1 = ndd * __ldg(&g_csr_w[j + 1]);
        float4 v0 = ((const float4*)(X + (size_t)s0 * HIDC))[lane];
        float4 v1 = ((const float4*)(X + (size_t)s1 * HIDC))[lane];
        acc.x += w0 * v0.x + w1 * v1.x;
        acc.y += w0 * v0.y + w1 * v1.y;
        acc.z += w0 * v0.z + w1 * v1.z;
        acc.w += w0 * v0.w + w1 * v1.w;
    }
    if (j < end) {
        int s0 = __ldg(&g_csr_src[j]);
        float w0 = ndd * __ldg(&g_csr_w[j]);
        float4 v0 = ((const float4*)(X + (size_t)s0 * HIDC))[lane];
        acc.x += w0 * v0.x; acc.y += w0 * v0.y; acc.z += w0 * v0.z; acc.w += w0 * v0.w;
    }
    ((float4*)(g_tx1 + (size_t)d * HIDC))[lane] = acc;
}

// ---------------- gather 2: g_th[d] = sum -dinv[s]*dinv[d] * relu(BN(g_h[s])) ----------------
__global__ void k_gather2() {
    int warp = (int)(((size_t)blockIdx.x * blockDim.x + threadIdx.x) >> 5);
    if (warp >= NN) return;
    int lane = threadIdx.x & 31;
    int d = warp;
    int j = g_rowptr[d], end = g_rowptr[d + 1];
    float ndd = -g_dinv[d];
    float4 sc = ((const float4*)g_scale)[lane];
    float4 sh = ((const float4*)g_shift)[lane];
    float4 acc = make_float4(0.f, 0.f, 0.f, 0.f);
    for (; j + 2 <= end; j += 2) {
        int s0 = __ldg(&g_csr_src[j]), s1 = __ldg(&g_csr_src[j + 1]);
        float w0 = ndd * __ldg(&g_csr_w[j]);
        float w1 = ndd * __ldg(&g_csr_w[j + 1]);
        float4 v0 = ((const float4*)(g_h + (size_t)s0 * HIDC))[lane];
        float4 v1 = ((const float4*)(g_h + (size_t)s1 * HIDC))[lane];
        v0.x = fmaxf(fmaf(v0.x, sc.x, sh.x), 0.f); v1.x = fmaxf(fmaf(v1.x, sc.x, sh.x), 0.f);
        v0.y = fmaxf(fmaf(v0.y, sc.y, sh.y), 0.f); v1.y = fmaxf(fmaf(v1.y, sc.y, sh.y), 0.f);
        v0.z = fmaxf(fmaf(v0.z, sc.z, sh.z), 0.f); v1.z = fmaxf(fmaf(v1.z, sc.z, sh.z), 0.f);
        v0.w = fmaxf(fmaf(v0.w, sc.w, sh.w), 0.f); v1.w = fmaxf(fmaf(v1.w, sc.w, sh.w), 0.f);
        acc.x += w0 * v0.x + w1 * v1.x;
        acc.y += w0 * v0.y + w1 * v1.y;
        acc.z += w0 * v0.z + w1 * v1.z;
        acc.w += w0 * v0.w + w1 * v1.w;
    }
    if (j < end) {
        int s0 = __ldg(&g_csr_src[j]);
        float w0 = ndd * __ldg(&g_csr_w[j]);
        float4 v0 = ((const float4*)(g_h + (size_t)s0 * HIDC))[lane];
        v0.x = fmaxf(fmaf(v0.x, sc.x, sh.x), 0.f);
        v0.y = fmaxf(fmaf(v0.y, sc.y, sh.y), 0.f);
        v0.z = fmaxf(fmaf(v0.z, sc.z, sh.z), 0.f);
        v0.w = fmaxf(fmaf(v0.w, sc.w, sh.w), 0.f);
        acc.x += w0 * v0.x; acc.y += w0 * v0.y; acc.z += w0 * v0.z; acc.w += w0 * v0.w;
    }
    ((float4*)(g_th + (size_t)d * HIDC))[lane] = acc;
}

// ---------------- GEMM1 (f32x2): g_h = X @ W0 + g_tx1 @ W1 + b ----------------
__global__ void __launch_bounds__(256) k_gemm1(const float* __restrict__ X,
                                               const float* __restrict__ W0,
                                               const float* __restrict__ W1,
                                               const float* __restrict__ bias) {
    extern __shared__ float sm[];
    float* W0s = sm;
    float* W1s = sm + 16384;
    float* xs  = sm + 32768;
    float* ts  = sm + 40960;
    int t = threadIdx.x;
    int row0 = blockIdx.x * 64;

    for (int i = t; i < 4096; i += 256) {
        ((float4*)W0s)[i] = ((const float4*)W0)[i];
        ((float4*)W1s)[i] = ((const float4*)W1)[i];
    }
    for (int i = t; i < 2048; i += 256) {
        int r = i >> 5, c4 = i & 31;
        int row = row0 + r;
        float4 vx = make_float4(0.f, 0.f, 0.f, 0.f), vt = vx;
        if (row < NN) {
            vx = ((const float4*)(X + (size_t)row * HIDC))[c4];
            vt = ((const float4*)(g_tx1 + (size_t)row * HIDC))[c4];
        }
        ((float4*)xs)[i] = vx;
        ((float4*)ts)[i] = vt;
    }
    __syncthreads();

    int tx = t & 15, ty = t >> 4;
    int cb = tx * 8, rb = ty * 4;
    unsigned long long acc[4][4];
#pragma unroll
    for (int r = 0; r < 4; r++)
#pragma unroll
        for (int j = 0; j < 4; j++) acc[r][j] = 0ULL;

    for (int k4 = 0; k4 < 32; k4++) {
        float4 av[4], bv[4];
#pragma unroll
        for (int r = 0; r < 4; r++) {
            av[r] = *(float4*)&xs[(rb + r) * HIDC + k4 * 4];
            bv[r] = *(float4*)&ts[(rb + r) * HIDC + k4 * 4];
        }
#pragma unroll
        for (int kk = 0; kk < 4; kk++) {
            int k = k4 * 4 + kk;
            ulonglong2 w0a = *(ulonglong2*)&W0s[k * HIDC + cb];
            ulonglong2 w0b = *(ulonglong2*)&W0s[k * HIDC + cb + 4];
            ulonglong2 w1a = *(ulonglong2*)&W1s[k * HIDC + cb];
            ulonglong2 w1b = *(ulonglong2*)&W1s[k * HIDC + cb + 4];
            unsigned long long a2[4], b2[4];
#pragma unroll
            for (int r = 0; r < 4; r++) {
                PACK2(a2[r], ((float*)&av[r])[kk]);
                PACK2(b2[r], ((float*)&bv[r])[kk]);
            }
#pragma unroll
            for (int r = 0; r < 4; r++) {
                FMA2(acc[r][0], a2[r], w0a.x);
                FMA2(acc[r][1], a2[r], w0a.y);
                FMA2(acc[r][2], a2[r], w0b.x);
                FMA2(acc[r][3], a2[r], w0b.y);
                FMA2(acc[r][0], b2[r], w1a.x);
                FMA2(acc[r][1], b2[r], w1a.y);
                FMA2(acc[r][2], b2[r], w1b.x);
                FMA2(acc[r][3], b2[r], w1b.y);
            }
        }
    }

    float bb[8];
#pragma unroll
    for (int j = 0; j < 8; j++) bb[j] = bias[cb + j];
#pragma unroll
    for (int r = 0; r < 4; r++) {
        int row = row0 + rb + r;
        if (row < NN) {
            float o[8];
#pragma unroll
            for (int j = 0; j < 4; j++) UNPACK2(o[2 * j], o[2 * j + 1], acc[r][j]);
            float4 o1 = make_float4(o[0] + bb[0], o[1] + bb[1], o[2] + bb[2], o[3] + bb[3]);
            float4 o2 = make_float4(o[4] + bb[4], o[5] + bb[5], o[6] + bb[6], o[7] + bb[7]);
            float4* op = (float4*)(g_h + (size_t)row * HIDC + cb);
            op[0] = o1;
            op[1] = o2;
        }
    }
}

// ---------------- BN column sums ----------------
__global__ void k_colsum() {
    __shared__ float s1[256], s2[256];
    int t = threadIdx.x;
    int c = t & 127, half = t >> 7;
    float s = 0.f, q = 0.f;
    for (int r = blockIdx.x * 2 + half; r < NN; r += gridDim.x * 2) {
        float v = g_h[(size_t)r * HIDC + c];
        s += v;
        q += v * v;
    }
    s1[t] = s;
    s2[t] = q;
    __syncthreads();
    if (half == 0) {
        atomicAdd(&g_sum[c], s1[t] + s1[t + 128]);
        atomicAdd(&g_sumsq[c], s2[t] + s2[t + 128]);
    }
}

__global__ void k_stats(const float* __restrict__ gamma, const float* __restrict__ beta) {
    int c = threadIdx.x;
    if (c < HIDC) {
        float mean = g_sum[c] * (1.0f / NN);
        float var = fmaxf(g_sumsq[c] * (1.0f / NN) - mean * mean, 0.f);
        float sc = gamma[c] * rsqrtf(var + EPSF);
        g_scale[c] = sc;
        g_shift[c] = beta[c] - mean * sc;
    }
}

// ---------------- GEMM2 (f32x2): [mu|ls] = bnrelu(h)@[Wmu0|Wls0] + th@[Wmu1|Wls1] + b ----------------
__global__ void __launch_bounds__(256) k_gemm2(const float* __restrict__ Wmu0,
                                               const float* __restrict__ Wmu1,
                                               const float* __restrict__ Wls0,
                                               const float* __restrict__ Wls1,
                                               const float* __restrict__ bmu,
                                               const float* __restrict__ bls,
                                               float* __restrict__ out) {
    extern __shared__ float sm[];
    float* W0s = sm;
    float* W1s = sm + 16384;
    float* xs  = sm + 32768;
    float* ts  = sm + 40960;
    int t = threadIdx.x;
    int row0 = blockIdx.x * 64;

    for (int i = t; i < 4096; i += 256) {
        int k = i >> 5, c4 = i & 31;
        float4 v0, v1;
        if (c4 < 16) {
            v0 = ((const float4*)(Wmu0 + (size_t)k * OUTC))[c4];
            v1 = ((const float4*)(Wmu1 + (size_t)k * OUTC))[c4];
        } else {
            v0 = ((const float4*)(Wls0 + (size_t)k * OUTC))[c4 - 16];
            v1 = ((const float4*)(Wls1 + (size_t)k * OUTC))[c4 - 16];
        }
        ((float4*)W0s)[i] = v0;
        ((float4*)W1s)[i] = v1;
    }
    for (int i = t; i < 2048; i += 256) {
        int r = i >> 5, c4 = i & 31;
        int row = row0 + r;
        float4 vx = make_float4(0.f, 0.f, 0.f, 0.f), vt = vx;
        if (row < NN) {
            vx = ((const float4*)(g_h + (size_t)row * HIDC))[c4];
            vt = ((const float4*)(g_th + (size_t)row * HIDC))[c4];
            float4 sc = ((const float4*)g_scale)[c4];
            float4 sh = ((const float4*)g_shift)[c4];
            vx.x = fmaxf(fmaf(vx.x, sc.x, sh.x), 0.f);
            vx.y = fmaxf(fmaf(vx.y, sc.y, sh.y), 0.f);
            vx.z = fmaxf(fmaf(vx.z, sc.z, sh.z), 0.f);
            vx.w = fmaxf(fmaf(vx.w, sc.w, sh.w), 0.f);
        }
        ((float4*)xs)[i] = vx;
        ((float4*)ts)[i] = vt;
    }
    __syncthreads();

    int tx = t & 15, ty = t >> 4;
    int cb = tx * 8, rb = ty * 4;
    unsigned long long acc[4][4];
#pragma unroll
    for (int r = 0; r < 4; r++)
#pragma unroll
        for (int j = 0; j < 4; j++) acc[r][j] = 0ULL;

    for (int k4 = 0; k4 < 32; k4++) {
        float4 av[4], bv[4];
#pragma unroll
        for (int r = 0; r < 4; r++) {
            av[r] = *(float4*)&xs[(rb + r) * HIDC + k4 * 4];
            bv[r] = *(float4*)&ts[(rb + r) * HIDC + k4 * 4];
        }
#pragma unroll
        for (int kk = 0; kk < 4; kk++) {
            int k = k4 * 4 + kk;
            ulonglong2 w0a = *(ulonglong2*)&W0s[k * HIDC + cb];
            ulonglong2 w0b = *(ulonglong2*)&W0s[k * HIDC + cb + 4];
            ulonglong2 w1a = *(ulonglong2*)&W1s[k * HIDC + cb];
            ulonglong2 w1b = *(ulonglong2*)&W1s[k * HIDC + cb + 4];
            unsigned long long a2[4], b2[4];
#pragma unroll
            for (int r = 0; r < 4; r++) {
                PACK2(a2[r], ((float*)&av[r])[kk]);
                PACK2(b2[r], ((float*)&bv[r])[kk]);
            }
#pragma unroll
            for (int r = 0; r < 4; r++) {
                FMA2(acc[r][0], a2[r], w0a.x);
                FMA2(acc[r][1], a2[r], w0a.y);
                FMA2(acc[r][2], a2[r], w0b.x);
                FMA2(acc[r][3], a2[r], w0b.y);
                FMA2(acc[r][0], b2[r], w1a.x);
                FMA2(acc[r][1], b2[r], w1a.y);
                FMA2(acc[r][2], b2[r], w1b.x);
                FMA2(acc[r][3], b2[r], w1b.y);
            }
        }
    }

    bool isMu = (tx < 8);
    int colLocal = isMu ? cb : (cb - 64);
    const float* bp = isMu ? bmu : bls;
    size_t obase = isMu ? 0 : (size_t)NN * OUTC;
    float bb[8];
#pragma unroll
    for (int j = 0; j < 8; j++) bb[j] = bp[colLocal + j];
#pragma unroll
    for (int r = 0; r < 4; r++) {
        int row = row0 + rb + r;
        if (row < NN) {
            float o[8];
#pragma unroll
            for (int j = 0; j < 4; j++) UNPACK2(o[2 * j], o[2 * j + 1], acc[r][j]);
            float4 o1 = make_float4(o[0] + bb[0], o[1] + bb[1], o[2] + bb[2], o[3] + bb[3]);
            float4 o2 = make_float4(o[4] + bb[4], o[5] + bb[5], o[6] + bb[6], o[7] + bb[7]);
            float4* op = (float4*)(out + obase + (size_t)row * OUTC + colLocal);
            op[0] = o1;
            op[1] = o2;
        }
    }
}

// ---------------- launch ----------------
extern "C" void kernel_launch(void* const* d_in, const int* in_sizes, int n_in,
                              void* d_out, int out_size) {
    const float* x     = (const float*)d_in[0];
    const int*   ei    = (const int*)d_in[1];
    const int*   src   = ei;
    const int*   dst   = ei + EE;
    const float* W1_0  = (const float*)d_in[2];
    const float* W1_1  = (const float*)d_in[3];
    const float* b1    = (const float*)d_in[4];
    const float* gamma = (const float*)d_in[5];
    const float* beta  = (const float*)d_in[6];
    const float* Wmu0  = (const float*)d_in[7];
    const float* Wmu1  = (const float*)d_in[8];
    const float* bmu   = (const float*)d_in[9];
    const float* Wls0  = (const float*)d_in[10];
    const float* Wls1  = (const float*)d_in[11];
    const float* bls   = (const float*)d_in[12];
    float* out = (float*)d_out;

    cudaFuncSetAttribute(k_gemm1, cudaFuncAttributeMaxDynamicSharedMemorySize, 196608);
    cudaFuncSetAttribute(k_gemm2, cudaFuncAttributeMaxDynamicSharedMemorySize, 196608);

    k_zero_small<<<(NN + 255) / 256, 256>>>();
    k_prep<<<(EE + 255) / 256, 256>>>(src, dst);
    k_dinv<<<(NN + 255) / 256, 256>>>();
    k_chunksum<<<NCHUNK, 256>>>();
    k_bscan<<<1, 32>>>();
    k_chunkscan<<<NCHUNK, 256>>>();
    k_fill<<<(EE + 255) / 256, 256>>>(src, dst);
    k_gather1<<<(NN * 32 + 255) / 256, 256>>>(x);
    k_gemm1<<<(NN + 63) / 64, 256, 196608>>>(x, W1_0, W1_1, b1);
    k_colsum<<<1024, 256>>>();
    k_stats<<<1, 128>>>(gamma, beta);
    k_gather2<<<(NN * 32 + 255) / 256, 256>>>();
    k_gemm2<<<(NN + 63) / 64, 256, 196608>>>(Wmu0, Wmu1, Wls0, Wls1, bmu, bls, out);
}

// round 4
// speedup vs baseline: 2.3667x; 1.7913x over previous
#include <cuda_runtime.h>
#include <cuda_bf16.h>
#include <cstdint>

#define NN 50000
#define EE 800000
#define HIDC 128
#define OUTC 64
#define EPSF 1e-5f
#define NCHUNK 196   // ceil(NN/256)

// ---------------- scratch (device globals) ----------------
__device__ float g_deg[NN];
__device__ float g_dinv[NN];
__device__ float g_tx1[(size_t)NN * HIDC];
__device__ float g_h[(size_t)NN * HIDC];
__device__ float g_th[(size_t)NN * HIDC];
__device__ float g_sum[HIDC];
__device__ float g_sumsq[HIDC];
__device__ float g_scale[HIDC];
__device__ float g_shift[HIDC];
// CSR scratch
__device__ int   g_cnt[NN];
__device__ int   g_bsum[NCHUNK];
__device__ int   g_boff[NCHUNK];
__device__ int   g_rowptr[NN + 1];
__device__ int   g_cursor[NN];
__device__ int   g_csr_src[EE];
__device__ float g_csr_w[EE];
// split-bf16 weights, pre-transposed: [N=128][K=256], K-major rows
__device__ __nv_bfloat16 g_w1hi[128 * 256];
__device__ __nv_bfloat16 g_w1lo[128 * 256];
__device__ __nv_bfloat16 g_w2hi[128 * 256];
__device__ __nv_bfloat16 g_w2lo[128 * 256];
__device__ float g_bias2[128];

// ---------------- mma / ldmatrix helpers (plain sm_80+ PTX; works on sm_103 base) ----------------
__device__ __forceinline__ uint32_t smem_u32(const void* p) {
    uint32_t a;
    asm("{ .reg .u64 t; cvta.to.shared.u64 t, %1; cvt.u32.u64 %0, t; }" : "=r"(a) : "l"(p));
    return a;
}
__device__ __forceinline__ void ldsm4(uint32_t* r, uint32_t addr) {
    asm volatile("ldmatrix.sync.aligned.m8n8.x4.shared.b16 {%0,%1,%2,%3}, [%4];"
                 : "=r"(r[0]), "=r"(r[1]), "=r"(r[2]), "=r"(r[3]) : "r"(addr));
}
__device__ __forceinline__ void mma_bf16(float* c, const uint32_t* a, const uint32_t* b) {
    asm volatile("mma.sync.aligned.m16n8k16.row.col.f32.bf16.bf16.f32 "
                 "{%0,%1,%2,%3}, {%4,%5,%6,%7}, {%8,%9}, {%0,%1,%2,%3};"
                 : "+f"(c[0]), "+f"(c[1]), "+f"(c[2]), "+f"(c[3])
                 : "r"(a[0]), "r"(a[1]), "r"(a[2]), "r"(a[3]), "r"(b[0]), "r"(b[1]));
}

// ---------------- small kernels ----------------
__global__ void k_zero_small() {
    int i = blockIdx.x * blockDim.x + threadIdx.x;
    if (i < NN) { g_deg[i] = 0.f; g_cnt[i] = 0; }
    if (i < HIDC) { g_sum[i] = 0.f; g_sumsq[i] = 0.f; }
}

__global__ void k_prep(const int* __restrict__ src, const int* __restrict__ dst) {
    int e = blockIdx.x * blockDim.x + threadIdx.x;
    if (e < EE) {
        atomicAdd(&g_deg[src[e]], 1.0f);
        atomicAdd(&g_cnt[dst[e]], 1);
    }
}

__global__ void k_dinv() {
    int i = blockIdx.x * blockDim.x + threadIdx.x;
    if (i < NN) {
        float d = g_deg[i];
        g_dinv[i] = (d > 0.5f) ? rsqrtf(d) : 0.f;
    }
}

__global__ void k_chunksum() {
    __shared__ int s[256];
    int c = blockIdx.x * 256 + threadIdx.x;
    s[threadIdx.x] = (c < NN) ? g_cnt[c] : 0;
    __syncthreads();
    for (int off = 128; off > 0; off >>= 1) {
        if (threadIdx.x < off) s[threadIdx.x] += s[threadIdx.x + off];
        __syncthreads();
    }
    if (threadIdx.x == 0) g_bsum[blockIdx.x] = s[0];
}

__global__ void k_bscan() {
    __shared__ int s[256];
    int t = threadIdx.x;
    int v = (t < NCHUNK) ? g_bsum[t] : 0;
    s[t] = v;
    __syncthreads();
    for (int off = 1; off < 256; off <<= 1) {
        int u = (t >= off) ? s[t - off] : 0;
        __syncthreads();
        s[t] += u;
        __syncthreads();
    }
    if (t < NCHUNK) g_boff[t] = s[t] - v;
    if (t == 0) g_rowptr[NN] = EE;
}

__global__ void k_chunkscan() {
    __shared__ int s[256];
    int c = blockIdx.x * 256 + threadIdx.x;
    int v = (c < NN) ? g_cnt[c] : 0;
    s[threadIdx.x] = v;
    __syncthreads();
    for (int off = 1; off < 256; off <<= 1) {
        int t = (threadIdx.x >= off) ? s[threadIdx.x - off] : 0;
        __syncthreads();
        s[threadIdx.x] += t;
        __syncthreads();
    }
    if (c < NN) {
        int excl = g_boff[blockIdx.x] + s[threadIdx.x] - v;
        g_rowptr[c] = excl;
        g_cursor[c] = excl;
    }
}

__global__ void k_fill(const int* __restrict__ src, const int* __restrict__ dst) {
    int e = blockIdx.x * blockDim.x + threadIdx.x;
    if (e < EE) {
        int s = src[e], d = dst[e];
        int p = atomicAdd(&g_cursor[d], 1);
        g_csr_src[p] = s;
        g_csr_w[p] = g_dinv[s];
    }
}

// ---------------- weight prep: transpose + split to bf16 hi/lo ----------------
__global__ void k_prepw(const float* __restrict__ W1_0, const float* __restrict__ W1_1,
                        const float* __restrict__ Wmu0, const float* __restrict__ Wmu1,
                        const float* __restrict__ Wls0, const float* __restrict__ Wls1,
                        const float* __restrict__ bmu, const float* __restrict__ bls) {
    int idx = blockIdx.x * blockDim.x + threadIdx.x;  // 0 .. 65535
    if (idx < 65536) {
        int stage = idx >> 15;
        int r = idx & 32767;
        int j = r >> 8, k = r & 255;  // j = output col (n), k = reduction idx
        float w;
        if (stage == 0) {
            w = (k < 128) ? W1_0[k * HIDC + j] : W1_1[(k - 128) * HIDC + j];
        } else {
            if (j < 64) w = (k < 128) ? Wmu0[k * OUTC + j] : Wmu1[(k - 128) * OUTC + j];
            else        w = (k < 128) ? Wls0[k * OUTC + (j - 64)] : Wls1[(k - 128) * OUTC + (j - 64)];
        }
        __nv_bfloat16 hi = __float2bfloat16(w);
        __nv_bfloat16 lo = __float2bfloat16(w - __bfloat162float(hi));
        if (stage == 0) { g_w1hi[r] = hi; g_w1lo[r] = lo; }
        else            { g_w2hi[r] = hi; g_w2lo[r] = lo; }
    }
    if (blockIdx.x == 0 && threadIdx.x < 128) {
        int j = threadIdx.x;
        g_bias2[j] = (j < 64) ? bmu[j] : bls[j - 64];
    }
}

// ---------------- gathers ----------------
__global__ void k_gather1(const float* __restrict__ X) {
    int warp = (int)(((size_t)blockIdx.x * blockDim.x + threadIdx.x) >> 5);
    if (warp >= NN) return;
    int lane = threadIdx.x & 31;
    int d = warp;
    int j = g_rowptr[d], end = g_rowptr[d + 1];
    float ndd = -g_dinv[d];
    float4 acc = make_float4(0.f, 0.f, 0.f, 0.f);
    for (; j + 4 <= end; j += 4) {
        int s0 = __ldg(&g_csr_src[j]),     s1 = __ldg(&g_csr_src[j + 1]);
        int s2 = __ldg(&g_csr_src[j + 2]), s3 = __ldg(&g_csr_src[j + 3]);
        float w0 = ndd * __ldg(&g_csr_w[j]),     w1 = ndd * __ldg(&g_csr_w[j + 1]);
        float w2 = ndd * __ldg(&g_csr_w[j + 2]), w3 = ndd * __ldg(&g_csr_w[j + 3]);
        float4 v0 = ((const float4*)(X + (size_t)s0 * HIDC))[lane];
        float4 v1 = ((const float4*)(X + (size_t)s1 * HIDC))[lane];
        float4 v2 = ((const float4*)(X + (size_t)s2 * HIDC))[lane];
        float4 v3 = ((const float4*)(X + (size_t)s3 * HIDC))[lane];
        acc.x += w0 * v0.x + w1 * v1.x + w2 * v2.x + w3 * v3.x;
        acc.y += w0 * v0.y + w1 * v1.y + w2 * v2.y + w3 * v3.y;
        acc.z += w0 * v0.z + w1 * v1.z + w2 * v2.z + w3 * v3.z;
        acc.w += w0 * v0.w + w1 * v1.w + w2 * v2.w + w3 * v3.w;
    }
    for (; j < end; j++) {
        int s0 = __ldg(&g_csr_src[j]);
        float w0 = ndd * __ldg(&g_csr_w[j]);
        float4 v0 = ((const float4*)(X + (size_t)s0 * HIDC))[lane];
        acc.x += w0 * v0.x; acc.y += w0 * v0.y; acc.z += w0 * v0.z; acc.w += w0 * v0.w;
    }
    ((float4*)(g_tx1 + (size_t)d * HIDC))[lane] = acc;
}

__global__ void k_gather2() {
    int warp = (int)(((size_t)blockIdx.x * blockDim.x + threadIdx.x) >> 5);
    if (warp >= NN) return;
    int lane = threadIdx.x & 31;
    int d = warp;
    int j = g_rowptr[d], end = g_rowptr[d + 1];
    float ndd = -g_dinv[d];
    float4 sc = ((const float4*)g_scale)[lane];
    float4 sh = ((const float4*)g_shift)[lane];
    float4 acc = make_float4(0.f, 0.f, 0.f, 0.f);
    for (; j + 2 <= end; j += 2) {
        int s0 = __ldg(&g_csr_src[j]), s1 = __ldg(&g_csr_src[j + 1]);
        float w0 = ndd * __ldg(&g_csr_w[j]);
        float w1 = ndd * __ldg(&g_csr_w[j + 1]);
        float4 v0 = ((const float4*)(g_h + (size_t)s0 * HIDC))[lane];
        float4 v1 = ((const float4*)(g_h + (size_t)s1 * HIDC))[lane];
        v0.x = fmaxf(fmaf(v0.x, sc.x, sh.x), 0.f); v1.x = fmaxf(fmaf(v1.x, sc.x, sh.x), 0.f);
        v0.y = fmaxf(fmaf(v0.y, sc.y, sh.y), 0.f); v1.y = fmaxf(fmaf(v1.y, sc.y, sh.y), 0.f);
        v0.z = fmaxf(fmaf(v0.z, sc.z, sh.z), 0.f); v1.z = fmaxf(fmaf(v1.z, sc.z, sh.z), 0.f);
        v0.w = fmaxf(fmaf(v0.w, sc.w, sh.w), 0.f); v1.w = fmaxf(fmaf(v1.w, sc.w, sh.w), 0.f);
        acc.x += w0 * v0.x + w1 * v1.x;
        acc.y += w0 * v0.y + w1 * v1.y;
        acc.z += w0 * v0.z + w1 * v1.z;
        acc.w += w0 * v0.w + w1 * v1.w;
    }
    if (j < end) {
        int s0 = __ldg(&g_csr_src[j]);
        float w0 = ndd * __ldg(&g_csr_w[j]);
        float4 v0 = ((const float4*)(g_h + (size_t)s0 * HIDC))[lane];
        v0.x = fmaxf(fmaf(v0.x, sc.x, sh.x), 0.f);
        v0.y = fmaxf(fmaf(v0.y, sc.y, sh.y), 0.f);
        v0.z = fmaxf(fmaf(v0.z, sc.z, sh.z), 0.f);
        v0.w = fmaxf(fmaf(v0.w, sc.w, sh.w), 0.f);
        acc.x += w0 * v0.x; acc.y += w0 * v0.y; acc.z += w0 * v0.z; acc.w += w0 * v0.w;
    }
    ((float4*)(g_th + (size_t)d * HIDC))[lane] = acc;
}

// ---------------- HMMA split-bf16 GEMM ----------------
#define TSTRIDE 272
#define TILE_B (128 * TSTRIDE)
#define OFF_AHI 0
#define OFF_ALO TILE_B
#define OFF_BHI (2 * TILE_B)
#define OFF_BLO (3 * TILE_B)
#define SMEM_TOT (4 * TILE_B)

__global__ void __launch_bounds__(256) k_tgemm(const float* __restrict__ Xext,
                                               const float* __restrict__ biasExt,
                                               float* __restrict__ outExt, int stage) {
    extern __shared__ char sm[];
    uint32_t sb = smem_u32(sm);
    int t = threadIdx.x;
    int row0 = blockIdx.x * 128;

    const float* A0 = stage ? g_h : Xext;
    const float* A1 = stage ? g_th : g_tx1;
    const __nv_bfloat16* Whi = stage ? g_w2hi : g_w1hi;
    const __nv_bfloat16* Wlo = stage ? g_w2lo : g_w1lo;
    const float* bias = stage ? g_bias2 : biasExt;

    int w = t >> 5, lane = t & 31;
    int warp_m = (w >> 1) * 32, warp_n = (w & 1) * 64;
    int gid = lane >> 2, tig = lane & 3;

    int arow = (lane & 7) + ((lane >> 3) & 1) * 8;
    int akoff = (lane >> 4) * 8;
    uint32_t aoff0 = (uint32_t)(warp_m + arow) * TSTRIDE + akoff * 2;
    uint32_t aoff1 = aoff0 + 16 * TSTRIDE;
    int brow = (lane & 7) + ((lane >> 4) & 1) * 8;
    int bkoff = ((lane >> 3) & 1) * 8;
    uint32_t boff = (uint32_t)(warp_n + brow) * TSTRIDE + bkoff * 2;

    float acc[2][8][4];
#pragma unroll
    for (int mt = 0; mt < 2; mt++)
#pragma unroll
        for (int j = 0; j < 8; j++)
#pragma unroll
            for (int q = 0; q < 4; q++) acc[mt][j][q] = 0.f;

    for (int c = 0; c < 2; c++) {
        if (c) __syncthreads();
        const float* A = c ? A1 : A0;
        for (int i = t; i < 8192; i += 256) {
            int row = i >> 6, col = (i & 63) * 2;
            int gr = row0 + row;
            float2 v = make_float2(0.f, 0.f);
            if (gr < NN) v = *(const float2*)(A + (size_t)gr * HIDC + col);
            if (stage && c == 0) {
                v.x = fmaxf(fmaf(v.x, g_scale[col], g_shift[col]), 0.f);
                v.y = fmaxf(fmaf(v.y, g_scale[col + 1], g_shift[col + 1]), 0.f);
            }
            __nv_bfloat16 h0 = __float2bfloat16(v.x);
            __nv_bfloat16 h1 = __float2bfloat16(v.y);
            __nv_bfloat16 l0 = __float2bfloat16(v.x - __bfloat162float(h0));
            __nv_bfloat16 l1 = __float2bfloat16(v.y - __bfloat162float(h1));
            uint32_t off = (uint32_t)row * TSTRIDE + col * 2;
            __nv_bfloat162 hv; hv.x = h0; hv.y = h1;
            __nv_bfloat162 lv; lv.x = l0; lv.y = l1;
            *(__nv_bfloat162*)(sm + OFF_AHI + off) = hv;
            *(__nv_bfloat162*)(sm + OFF_ALO + off) = lv;
        }
        for (int i = t; i < 8192; i += 256) {
            int row = i >> 6, col = (i & 63) * 2;
            __nv_bfloat162 hv = *(const __nv_bfloat162*)(Whi + row * 256 + c * 128 + col);
            __nv_bfloat162 lv = *(const __nv_bfloat162*)(Wlo + row * 256 + c * 128 + col);
            uint32_t off = (uint32_t)row * TSTRIDE + col * 2;
            *(__nv_bfloat162*)(sm + OFF_BHI + off) = hv;
            *(__nv_bfloat162*)(sm + OFF_BLO + off) = lv;
        }
        __syncthreads();

#pragma unroll
        for (int ks = 0; ks < 8; ks++) {
            uint32_t k2 = (uint32_t)ks * 32;
            uint32_t ah0[4], ah1[4], al0[4], al1[4];
            ldsm4(ah0, sb + OFF_AHI + aoff0 + k2);
            ldsm4(ah1, sb + OFF_AHI + aoff1 + k2);
            ldsm4(al0, sb + OFF_ALO + aoff0 + k2);
            ldsm4(al1, sb + OFF_ALO + aoff1 + k2);
#pragma unroll
            for (int np = 0; np < 4; np++) {
                uint32_t bh[4], bl[4];
                uint32_t bo = boff + (uint32_t)np * 16 * TSTRIDE + k2;
                ldsm4(bh, sb + OFF_BHI + bo);
                ldsm4(bl, sb + OFF_BLO + bo);
                mma_bf16(acc[0][2 * np],     ah0, bh);
                mma_bf16(acc[0][2 * np + 1], ah0, bh + 2);
                mma_bf16(acc[1][2 * np],     ah1, bh);
                mma_bf16(acc[1][2 * np + 1], ah1, bh + 2);
                mma_bf16(acc[0][2 * np],     al0, bh);
                mma_bf16(acc[0][2 * np + 1], al0, bh + 2);
                mma_bf16(acc[1][2 * np],     al1, bh);
                mma_bf16(acc[1][2 * np + 1], al1, bh + 2);
                mma_bf16(acc[0][2 * np],     ah0, bl);
                mma_bf16(acc[0][2 * np + 1], ah0, bl + 2);
                mma_bf16(acc[1][2 * np],     ah1, bl);
                mma_bf16(acc[1][2 * np + 1], ah1, bl + 2);
            }
        }
    }

#pragma unroll
    for (int j = 0; j < 8; j++) {
        int n = warp_n + j * 8 + tig * 2;
        float b0 = bias[n], b1 = bias[n + 1];
#pragma unroll
        for (int mt = 0; mt < 2; mt++) {
            int r1 = row0 + warp_m + mt * 16 + gid;
            int r2 = r1 + 8;
            float2 v1 = make_float2(acc[mt][j][0] + b0, acc[mt][j][1] + b1);
            float2 v2 = make_float2(acc[mt][j][2] + b0, acc[mt][j][3] + b1);
            if (stage == 0) {
                if (r1 < NN) *(float2*)(g_h + (size_t)r1 * HIDC + n) = v1;
                if (r2 < NN) *(float2*)(g_h + (size_t)r2 * HIDC + n) = v2;
            } else {
                int nl = (n < 64) ? n : (n - 64);
                size_t obase = (n < 64) ? 0 : (size_t)NN * OUTC;
                if (r1 < NN) *(float2*)(outExt + obase + (size_t)r1 * OUTC + nl) = v1;
                if (r2 < NN) *(float2*)(outExt + obase + (size_t)r2 * OUTC + nl) = v2;
            }
        }
    }
}

// ---------------- BN column sums ----------------
__global__ void k_colsum() {
    __shared__ float s1[256], s2[256];
    int t = threadIdx.x;
    int c = t & 127, half = t >> 7;
    float s = 0.f, q = 0.f;
    for (int r = blockIdx.x * 2 + half; r < NN; r += gridDim.x * 2) {
        float v = g_h[(size_t)r * HIDC + c];
        s += v;
        q += v * v;
    }
    s1[t] = s;
    s2[t] = q;
    __syncthreads();
    if (half == 0) {
        atomicAdd(&g_sum[c], s1[t] + s1[t + 128]);
        atomicAdd(&g_sumsq[c], s2[t] + s2[t + 128]);
    }
}

__global__ void k_stats(const float* __restrict__ gamma, const float* __restrict__ beta) {
    int c = threadIdx.x;
    if (c < HIDC) {
        float mean = g_sum[c] * (1.0f / NN);
        float var = fmaxf(g_sumsq[c] * (1.0f / NN) - mean * mean, 0.f);
        float sc = gamma[c] * rsqrtf(var + EPSF);
        g_scale[c] = sc;
        g_shift[c] = beta[c] - mean * sc;
    }
}

// ---------------- launch ----------------
extern "C" void kernel_launch(void* const* d_in, const int* in_sizes, int n_in,
                              void* d_out, int out_size) {
    const float* x     = (const float*)d_in[0];
    const int*   ei    = (const int*)d_in[1];
    const int*   src   = ei;
    const int*   dst   = ei + EE;
    const float* W1_0  = (const float*)d_in[2];
    const float* W1_1  = (const float*)d_in[3];
    const float* b1    = (const float*)d_in[4];
    const float* gamma = (const float*)d_in[5];
    const float* beta  = (const float*)d_in[6];
    const float* Wmu0  = (const float*)d_in[7];
    const float* Wmu1  = (const float*)d_in[8];
    const float* bmu   = (const float*)d_in[9];
    const float* Wls0  = (const float*)d_in[10];
    const float* Wls1  = (const float*)d_in[11];
    const float* bls   = (const float*)d_in[12];
    float* out = (float*)d_out;

    cudaFuncSetAttribute(k_tgemm, cudaFuncAttributeMaxDynamicSharedMemorySize, SMEM_TOT);

    k_zero_small<<<(NN + 255) / 256, 256>>>();
    k_prep<<<(EE + 255) / 256, 256>>>(src, dst);
    k_dinv<<<(NN + 255) / 256, 256>>>();
    k_chunksum<<<NCHUNK, 256>>>();
    k_bscan<<<1, 256>>>();
    k_chunkscan<<<NCHUNK, 256>>>();
    k_fill<<<(EE + 255) / 256, 256>>>(src, dst);
    k_prepw<<<256, 256>>>(W1_0, W1_1, Wmu0, Wmu1, Wls0, Wls1, bmu, bls);
    k_gather1<<<(NN * 32 + 255) / 256, 256>>>(x);
    k_tgemm<<<(NN + 127) / 128, 256, SMEM_TOT>>>(x, b1, nullptr, 0);
    k_colsum<<<1024, 256>>>();
    k_stats<<<1, 128>>>(gamma, beta);
    k_gather2<<<(NN * 32 + 255) / 256, 256>>>();
    k_tgemm<<<(NN + 127) / 128, 256, SMEM_TOT>>>(nullptr, nullptr, out, 1);
}

// round 5
// speedup vs baseline: 2.4351x; 1.0289x over previous
#include <cuda_runtime.h>
#include <cuda_bf16.h>
#include <cstdint>

#define NN 50000
#define EE 800000
#define HIDC 128
#define OUTC 64
#define EPSF 1e-5f
#define NCHUNK 196   // ceil(NN/256)

// ---------------- scratch (device globals) ----------------
__device__ float g_deg[NN];
__device__ float g_dinv[NN];
__device__ float g_tx1[(size_t)NN * HIDC];
__device__ float g_h[(size_t)NN * HIDC];
__device__ float g_th[(size_t)NN * HIDC];
__device__ float g_sum[HIDC];
__device__ float g_sumsq[HIDC];
__device__ float g_scale[HIDC];
__device__ float g_shift[HIDC];
// CSR scratch
__device__ int   g_cnt[NN];
__device__ int   g_bsum[NCHUNK];
__device__ int   g_boff[NCHUNK];
__device__ int   g_rowptr[NN + 1];
__device__ int   g_cursor[NN];
__device__ int   g_csr_src[EE];
__device__ float g_csr_w[EE];
// split-bf16 weights, pre-transposed: [N=128][K=256], K-major rows
__device__ __nv_bfloat16 g_w1hi[128 * 256];
__device__ __nv_bfloat16 g_w1lo[128 * 256];
__device__ __nv_bfloat16 g_w2hi[128 * 256];
__device__ __nv_bfloat16 g_w2lo[128 * 256];
__device__ float g_bias2[128];

// ---------------- mma / ldmatrix helpers ----------------
__device__ __forceinline__ uint32_t smem_u32(const void* p) {
    uint32_t a;
    asm("{ .reg .u64 t; cvta.to.shared.u64 t, %1; cvt.u32.u64 %0, t; }" : "=r"(a) : "l"(p));
    return a;
}
__device__ __forceinline__ void ldsm4(uint32_t* r, uint32_t addr) {
    asm volatile("ldmatrix.sync.aligned.m8n8.x4.shared.b16 {%0,%1,%2,%3}, [%4];"
                 : "=r"(r[0]), "=r"(r[1]), "=r"(r[2]), "=r"(r[3]) : "r"(addr));
}
__device__ __forceinline__ void mma_bf16(float* c, const uint32_t* a, const uint32_t* b) {
    asm volatile("mma.sync.aligned.m16n8k16.row.col.f32.bf16.bf16.f32 "
                 "{%0,%1,%2,%3}, {%4,%5,%6,%7}, {%8,%9}, {%0,%1,%2,%3};"
                 : "+f"(c[0]), "+f"(c[1]), "+f"(c[2]), "+f"(c[3])
                 : "r"(a[0]), "r"(a[1]), "r"(a[2]), "r"(a[3]), "r"(b[0]), "r"(b[1]));
}

// ---------------- small kernels ----------------
__global__ void k_zero_small() {
    int i = blockIdx.x * blockDim.x + threadIdx.x;
    if (i < NN) { g_deg[i] = 0.f; g_cnt[i] = 0; }
    if (i < HIDC) { g_sum[i] = 0.f; g_sumsq[i] = 0.f; }
}

__global__ void k_prep(const int* __restrict__ src, const int* __restrict__ dst) {
    int e = blockIdx.x * blockDim.x + threadIdx.x;
    if (e < EE) {
        atomicAdd(&g_deg[src[e]], 1.0f);
        atomicAdd(&g_cnt[dst[e]], 1);
    }
}

// fused: dinv + per-chunk count sums
__global__ void k_csrprep() {
    __shared__ int s[256];
    int c = blockIdx.x * 256 + threadIdx.x;
    int v = 0;
    if (c < NN) {
        v = g_cnt[c];
        float d = g_deg[c];
        g_dinv[c] = (d > 0.5f) ? rsqrtf(d) : 0.f;
    }
    s[threadIdx.x] = v;
    __syncthreads();
    for (int off = 128; off > 0; off >>= 1) {
        if (threadIdx.x < off) s[threadIdx.x] += s[threadIdx.x + off];
        __syncthreads();
    }
    if (threadIdx.x == 0) g_bsum[blockIdx.x] = s[0];
}

__global__ void k_bscan() {
    __shared__ int s[256];
    int t = threadIdx.x;
    int v = (t < NCHUNK) ? g_bsum[t] : 0;
    s[t] = v;
    __syncthreads();
    for (int off = 1; off < 256; off <<= 1) {
        int u = (t >= off) ? s[t - off] : 0;
        __syncthreads();
        s[t] += u;
        __syncthreads();
    }
    if (t < NCHUNK) g_boff[t] = s[t] - v;
    if (t == 0) g_rowptr[NN] = EE;
}

__global__ void k_chunkscan() {
    __shared__ int s[256];
    int c = blockIdx.x * 256 + threadIdx.x;
    int v = (c < NN) ? g_cnt[c] : 0;
    s[threadIdx.x] = v;
    __syncthreads();
    for (int off = 1; off < 256; off <<= 1) {
        int t = (threadIdx.x >= off) ? s[threadIdx.x - off] : 0;
        __syncthreads();
        s[threadIdx.x] += t;
        __syncthreads();
    }
    if (c < NN) {
        int excl = g_boff[blockIdx.x] + s[threadIdx.x] - v;
        g_rowptr[c] = excl;
        g_cursor[c] = excl;
    }
}

__global__ void k_fill(const int* __restrict__ src, const int* __restrict__ dst) {
    int e = blockIdx.x * blockDim.x + threadIdx.x;
    if (e < EE) {
        int s = src[e], d = dst[e];
        int p = atomicAdd(&g_cursor[d], 1);
        g_csr_src[p] = s;
        g_csr_w[p] = g_dinv[s];
    }
}

// ---------------- weight prep: transpose + split to bf16 hi/lo ----------------
__global__ void k_prepw(const float* __restrict__ W1_0, const float* __restrict__ W1_1,
                        const float* __restrict__ Wmu0, const float* __restrict__ Wmu1,
                        const float* __restrict__ Wls0, const float* __restrict__ Wls1,
                        const float* __restrict__ bmu, const float* __restrict__ bls) {
    int idx = blockIdx.x * blockDim.x + threadIdx.x;
    if (idx < 65536) {
        int stage = idx >> 15;
        int r = idx & 32767;
        int j = r >> 8, k = r & 255;
        float w;
        if (stage == 0) {
            w = (k < 128) ? W1_0[k * HIDC + j] : W1_1[(k - 128) * HIDC + j];
        } else {
            if (j < 64) w = (k < 128) ? Wmu0[k * OUTC + j] : Wmu1[(k - 128) * OUTC + j];
            else        w = (k < 128) ? Wls0[k * OUTC + (j - 64)] : Wls1[(k - 128) * OUTC + (j - 64)];
        }
        __nv_bfloat16 hi = __float2bfloat16(w);
        __nv_bfloat16 lo = __float2bfloat16(w - __bfloat162float(hi));
        if (stage == 0) { g_w1hi[r] = hi; g_w1lo[r] = lo; }
        else            { g_w2hi[r] = hi; g_w2lo[r] = lo; }
    }
    if (blockIdx.x == 0 && threadIdx.x < 128) {
        int j = threadIdx.x;
        g_bias2[j] = (j < 64) ? bmu[j] : bls[j - 64];
    }
}

// ---------------- gather 1 ----------------
__global__ void k_gather1(const float* __restrict__ X) {
    int warp = (int)(((size_t)blockIdx.x * blockDim.x + threadIdx.x) >> 5);
    if (warp >= NN) return;
    int lane = threadIdx.x & 31;
    int d = warp;
    int j = g_rowptr[d], end = g_rowptr[d + 1];
    float ndd = -g_dinv[d];
    float4 acc = make_float4(0.f, 0.f, 0.f, 0.f);
    for (; j + 4 <= end; j += 4) {
        int s0 = __ldg(&g_csr_src[j]),     s1 = __ldg(&g_csr_src[j + 1]);
        int s2 = __ldg(&g_csr_src[j + 2]), s3 = __ldg(&g_csr_src[j + 3]);
        float w0 = ndd * __ldg(&g_csr_w[j]),     w1 = ndd * __ldg(&g_csr_w[j + 1]);
        float w2 = ndd * __ldg(&g_csr_w[j + 2]), w3 = ndd * __ldg(&g_csr_w[j + 3]);
        float4 v0 = ((const float4*)(X + (size_t)s0 * HIDC))[lane];
        float4 v1 = ((const float4*)(X + (size_t)s1 * HIDC))[lane];
        float4 v2 = ((const float4*)(X + (size_t)s2 * HIDC))[lane];
        float4 v3 = ((const float4*)(X + (size_t)s3 * HIDC))[lane];
        acc.x += w0 * v0.x + w1 * v1.x + w2 * v2.x + w3 * v3.x;
        acc.y += w0 * v0.y + w1 * v1.y + w2 * v2.y + w3 * v3.y;
        acc.z += w0 * v0.z + w1 * v1.z + w2 * v2.z + w3 * v3.z;
        acc.w += w0 * v0.w + w1 * v1.w + w2 * v2.w + w3 * v3.w;
    }
    for (; j < end; j++) {
        int s0 = __ldg(&g_csr_src[j]);
        float w0 = ndd * __ldg(&g_csr_w[j]);
        float4 v0 = ((const float4*)(X + (size_t)s0 * HIDC))[lane];
        acc.x += w0 * v0.x; acc.y += w0 * v0.y; acc.z += w0 * v0.z; acc.w += w0 * v0.w;
    }
    ((float4*)(g_tx1 + (size_t)d * HIDC))[lane] = acc;
}

// ---------------- gather 2 (fused BN stats -> scale/shift; unroll 4) ----------------
__global__ void __launch_bounds__(256) k_gather2(const float* __restrict__ gamma,
                                                 const float* __restrict__ beta) {
    __shared__ float s_sc[128], s_sh[128];
    int t = threadIdx.x;
    if (t < 128) {
        float mean = g_sum[t] * (1.0f / NN);
        float var = fmaxf(g_sumsq[t] * (1.0f / NN) - mean * mean, 0.f);
        float sc = gamma[t] * rsqrtf(var + EPSF);
        float shv = beta[t] - mean * sc;
        s_sc[t] = sc;
        s_sh[t] = shv;
        if (blockIdx.x == 0) { g_scale[t] = sc; g_shift[t] = shv; }
    }
    __syncthreads();

    int warp = (int)(((size_t)blockIdx.x * blockDim.x + t) >> 5);
    if (warp >= NN) return;
    int lane = t & 31;
    int d = warp;
    int j = g_rowptr[d], end = g_rowptr[d + 1];
    float ndd = -g_dinv[d];
    float4 sc = *(float4*)&s_sc[lane * 4];
    float4 sh = *(float4*)&s_sh[lane * 4];
    float4 acc = make_float4(0.f, 0.f, 0.f, 0.f);
    for (; j + 4 <= end; j += 4) {
        int s0 = __ldg(&g_csr_src[j]),     s1 = __ldg(&g_csr_src[j + 1]);
        int s2 = __ldg(&g_csr_src[j + 2]), s3 = __ldg(&g_csr_src[j + 3]);
        float w0 = ndd * __ldg(&g_csr_w[j]),     w1 = ndd * __ldg(&g_csr_w[j + 1]);
        float w2 = ndd * __ldg(&g_csr_w[j + 2]), w3 = ndd * __ldg(&g_csr_w[j + 3]);
        float4 v0 = ((const float4*)(g_h + (size_t)s0 * HIDC))[lane];
        float4 v1 = ((const float4*)(g_h + (size_t)s1 * HIDC))[lane];
        float4 v2 = ((const float4*)(g_h + (size_t)s2 * HIDC))[lane];
        float4 v3 = ((const float4*)(g_h + (size_t)s3 * HIDC))[lane];
        v0.x = fmaxf(fmaf(v0.x, sc.x, sh.x), 0.f); v1.x = fmaxf(fmaf(v1.x, sc.x, sh.x), 0.f);
        v2.x = fmaxf(fmaf(v2.x, sc.x, sh.x), 0.f); v3.x = fmaxf(fmaf(v3.x, sc.x, sh.x), 0.f);
        v0.y = fmaxf(fmaf(v0.y, sc.y, sh.y), 0.f); v1.y = fmaxf(fmaf(v1.y, sc.y, sh.y), 0.f);
        v2.y = fmaxf(fmaf(v2.y, sc.y, sh.y), 0.f); v3.y = fmaxf(fmaf(v3.y, sc.y, sh.y), 0.f);
        v0.z = fmaxf(fmaf(v0.z, sc.z, sh.z), 0.f); v1.z = fmaxf(fmaf(v1.z, sc.z, sh.z), 0.f);
        v2.z = fmaxf(fmaf(v2.z, sc.z, sh.z), 0.f); v3.z = fmaxf(fmaf(v3.z, sc.z, sh.z), 0.f);
        v0.w = fmaxf(fmaf(v0.w, sc.w, sh.w), 0.f); v1.w = fmaxf(fmaf(v1.w, sc.w, sh.w), 0.f);
        v2.w = fmaxf(fmaf(v2.w, sc.w, sh.w), 0.f); v3.w = fmaxf(fmaf(v3.w, sc.w, sh.w), 0.f);
        acc.x += w0 * v0.x + w1 * v1.x + w2 * v2.x + w3 * v3.x;
        acc.y += w0 * v0.y + w1 * v1.y + w2 * v2.y + w3 * v3.y;
        acc.z += w0 * v0.z + w1 * v1.z + w2 * v2.z + w3 * v3.z;
        acc.w += w0 * v0.w + w1 * v1.w + w2 * v2.w + w3 * v3.w;
    }
    for (; j < end; j++) {
        int s0 = __ldg(&g_csr_src[j]);
        float w0 = ndd * __ldg(&g_csr_w[j]);
        float4 v0 = ((const float4*)(g_h + (size_t)s0 * HIDC))[lane];
        v0.x = fmaxf(fmaf(v0.x, sc.x, sh.x), 0.f);
        v0.y = fmaxf(fmaf(v0.y, sc.y, sh.y), 0.f);
        v0.z = fmaxf(fmaf(v0.z, sc.z, sh.z), 0.f);
        v0.w = fmaxf(fmaf(v0.w, sc.w, sh.w), 0.f);
        acc.x += w0 * v0.x; acc.y += w0 * v0.y; acc.z += w0 * v0.z; acc.w += w0 * v0.w;
    }
    ((float4*)(g_th + (size_t)d * HIDC))[lane] = acc;
}

// ---------------- HMMA split-bf16 GEMM (stage 0 fuses BN column sums) ----------------
#define TSTRIDE 272
#define TILE_B (128 * TSTRIDE)
#define OFF_AHI 0
#define OFF_ALO TILE_B
#define OFF_BHI (2 * TILE_B)
#define OFF_BLO (3 * TILE_B)
#define SMEM_TOT (4 * TILE_B)

__global__ void __launch_bounds__(256) k_tgemm(const float* __restrict__ Xext,
                                               const float* __restrict__ biasExt,
                                               float* __restrict__ outExt, int stage) {
    extern __shared__ char sm[];
    __shared__ float s_cs[128], s_cq[128];
    uint32_t sb = smem_u32(sm);
    int t = threadIdx.x;
    int row0 = blockIdx.x * 128;

    if (stage == 0 && t < 128) { s_cs[t] = 0.f; s_cq[t] = 0.f; }

    const float* A0 = stage ? g_h : Xext;
    const float* A1 = stage ? g_th : g_tx1;
    const __nv_bfloat16* Whi = stage ? g_w2hi : g_w1hi;
    const __nv_bfloat16* Wlo = stage ? g_w2lo : g_w1lo;
    const float* bias = stage ? g_bias2 : biasExt;

    int w = t >> 5, lane = t & 31;
    int warp_m = (w >> 1) * 32, warp_n = (w & 1) * 64;
    int gid = lane >> 2, tig = lane & 3;

    int arow = (lane & 7) + ((lane >> 3) & 1) * 8;
    int akoff = (lane >> 4) * 8;
    uint32_t aoff0 = (uint32_t)(warp_m + arow) * TSTRIDE + akoff * 2;
    uint32_t aoff1 = aoff0 + 16 * TSTRIDE;
    int brow = (lane & 7) + ((lane >> 4) & 1) * 8;
    int bkoff = ((lane >> 3) & 1) * 8;
    uint32_t boff = (uint32_t)(warp_n + brow) * TSTRIDE + bkoff * 2;

    float acc[2][8][4];
#pragma unroll
    for (int mt = 0; mt < 2; mt++)
#pragma unroll
        for (int j = 0; j < 8; j++)
#pragma unroll
            for (int q = 0; q < 4; q++) acc[mt][j][q] = 0.f;

    for (int c = 0; c < 2; c++) {
        if (c) __syncthreads();
        const float* A = c ? A1 : A0;
        for (int i = t; i < 8192; i += 256) {
            int row = i >> 6, col = (i & 63) * 2;
            int gr = row0 + row;
            float2 v = make_float2(0.f, 0.f);
            if (gr < NN) v = *(const float2*)(A + (size_t)gr * HIDC + col);
            if (stage && c == 0) {
                v.x = fmaxf(fmaf(v.x, g_scale[col], g_shift[col]), 0.f);
                v.y = fmaxf(fmaf(v.y, g_scale[col + 1], g_shift[col + 1]), 0.f);
            }
            __nv_bfloat16 h0 = __float2bfloat16(v.x);
            __nv_bfloat16 h1 = __float2bfloat16(v.y);
            __nv_bfloat16 l0 = __float2bfloat16(v.x - __bfloat162float(h0));
            __nv_bfloat16 l1 = __float2bfloat16(v.y - __bfloat162float(h1));
            uint32_t off = (uint32_t)row * TSTRIDE + col * 2;
            __nv_bfloat162 hv; hv.x = h0; hv.y = h1;
            __nv_bfloat162 lv; lv.x = l0; lv.y = l1;
            *(__nv_bfloat162*)(sm + OFF_AHI + off) = hv;
            *(__nv_bfloat162*)(sm + OFF_ALO + off) = lv;
        }
        for (int i = t; i < 8192; i += 256) {
            int row = i >> 6, col = (i & 63) * 2;
            __nv_bfloat162 hv = *(const __nv_bfloat162*)(Whi + row * 256 + c * 128 + col);
            __nv_bfloat162 lv = *(const __nv_bfloat162*)(Wlo + row * 256 + c * 128 + col);
            uint32_t off = (uint32_t)row * TSTRIDE + col * 2;
            *(__nv_bfloat162*)(sm + OFF_BHI + off) = hv;
            *(__nv_bfloat162*)(sm + OFF_BLO + off) = lv;
        }
        __syncthreads();

#pragma unroll
        for (int ks = 0; ks < 8; ks++) {
            uint32_t k2 = (uint32_t)ks * 32;
            uint32_t ah0[4], ah1[4], al0[4], al1[4];
            ldsm4(ah0, sb + OFF_AHI + aoff0 + k2);
            ldsm4(ah1, sb + OFF_AHI + aoff1 + k2);
            ldsm4(al0, sb + OFF_ALO + aoff0 + k2);
            ldsm4(al1, sb + OFF_ALO + aoff1 + k2);
#pragma unroll
            for (int np = 0; np < 4; np++) {
                uint32_t bh[4], bl[4];
                uint32_t bo = boff + (uint32_t)np * 16 * TSTRIDE + k2;
                ldsm4(bh, sb + OFF_BHI + bo);
                ldsm4(bl, sb + OFF_BLO + bo);
                mma_bf16(acc[0][2 * np],     ah0, bh);
                mma_bf16(acc[0][2 * np + 1], ah0, bh + 2);
                mma_bf16(acc[1][2 * np],     ah1, bh);
                mma_bf16(acc[1][2 * np + 1], ah1, bh + 2);
                mma_bf16(acc[0][2 * np],     al0, bh);
                mma_bf16(acc[0][2 * np + 1], al0, bh + 2);
                mma_bf16(acc[1][2 * np],     al1, bh);
                mma_bf16(acc[1][2 * np + 1], al1, bh + 2);
                mma_bf16(acc[0][2 * np],     ah0, bl);
                mma_bf16(acc[0][2 * np + 1], ah0, bl + 2);
                mma_bf16(acc[1][2 * np],     ah1, bl);
                mma_bf16(acc[1][2 * np + 1], ah1, bl + 2);
            }
        }
    }

#pragma unroll
    for (int j = 0; j < 8; j++) {
        int n = warp_n + j * 8 + tig * 2;
        float b0 = bias[n], b1 = bias[n + 1];
#pragma unroll
        for (int mt = 0; mt < 2; mt++) {
            int r1 = row0 + warp_m + mt * 16 + gid;
            int r2 = r1 + 8;
            float2 v1 = make_float2(acc[mt][j][0] + b0, acc[mt][j][1] + b1);
            float2 v2 = make_float2(acc[mt][j][2] + b0, acc[mt][j][3] + b1);
            if (stage == 0) {
                if (r1 < NN) *(float2*)(g_h + (size_t)r1 * HIDC + n) = v1;
                if (r2 < NN) *(float2*)(g_h + (size_t)r2 * HIDC + n) = v2;
                // fused BN column sums: reduce over the 8 gid-lanes, then smem atomics
                float sx = (r1 < NN ? v1.x : 0.f) + (r2 < NN ? v2.x : 0.f);
                float sy = (r1 < NN ? v1.y : 0.f) + (r2 < NN ? v2.y : 0.f);
                float qx = (r1 < NN ? v1.x * v1.x : 0.f) + (r2 < NN ? v2.x * v2.x : 0.f);
                float qy = (r1 < NN ? v1.y * v1.y : 0.f) + (r2 < NN ? v2.y * v2.y : 0.f);
#pragma unroll
                for (int off = 4; off <= 16; off <<= 1) {
                    sx += __shfl_xor_sync(0xffffffffu, sx, off);
                    sy += __shfl_xor_sync(0xffffffffu, sy, off);
                    qx += __shfl_xor_sync(0xffffffffu, qx, off);
                    qy += __shfl_xor_sync(0xffffffffu, qy, off);
                }
                if (gid == 0) {
                    atomicAdd(&s_cs[n], sx);
                    atomicAdd(&s_cs[n + 1], sy);
                    atomicAdd(&s_cq[n], qx);
                    atomicAdd(&s_cq[n + 1], qy);
                }
            } else {
                int nl = (n < 64) ? n : (n - 64);
                size_t obase = (n < 64) ? 0 : (size_t)NN * OUTC;
                if (r1 < NN) *(float2*)(outExt + obase + (size_t)r1 * OUTC + nl) = v1;
                if (r2 < NN) *(float2*)(outExt + obase + (size_t)r2 * OUTC + nl) = v2;
            }
        }
    }

    if (stage == 0) {
        __syncthreads();
        if (t < 128) {
            atomicAdd(&g_sum[t], s_cs[t]);
            atomicAdd(&g_sumsq[t], s_cq[t]);
        }
    }
}

// ---------------- launch ----------------
extern "C" void kernel_launch(void* const* d_in, const int* in_sizes, int n_in,
                              void* d_out, int out_size) {
    const float* x     = (const float*)d_in[0];
    const int*   ei    = (const int*)d_in[1];
    const int*   src   = ei;
    const int*   dst   = ei + EE;
    const float* W1_0  = (const float*)d_in[2];
    const float* W1_1  = (const float*)d_in[3];
    const float* b1    = (const float*)d_in[4];
    const float* gamma = (const float*)d_in[5];
    const float* beta  = (const float*)d_in[6];
    const float* Wmu0  = (const float*)d_in[7];
    const float* Wmu1  = (const float*)d_in[8];
    const float* bmu   = (const float*)d_in[9];
    const float* Wls0  = (const float*)d_in[10];
    const float* Wls1  = (const float*)d_in[11];
    const float* bls   = (const float*)d_in[12];
    float* out = (float*)d_out;

    cudaFuncSetAttribute(k_tgemm, cudaFuncAttributeMaxDynamicSharedMemorySize, SMEM_TOT);

    k_zero_small<<<(NN + 255) / 256, 256>>>();
    k_prep<<<(EE + 255) / 256, 256>>>(src, dst);
    k_prepw<<<256, 256>>>(W1_0, W1_1, Wmu0, Wmu1, Wls0, Wls1, bmu, bls);
    k_csrprep<<<NCHUNK, 256>>>();
    k_bscan<<<1, 256>>>();
    k_chunkscan<<<NCHUNK, 256>>>();
    k_fill<<<(EE + 255) / 256, 256>>>(src, dst);
    k_gather1<<<(NN * 32 + 255) / 256, 256>>>(x);
    k_tgemm<<<(NN + 127) / 128, 256, SMEM_TOT>>>(x, b1, nullptr, 0);
    k_gather2<<<(NN * 32 + 255) / 256, 256>>>(gamma, beta);
    k_tgemm<<<(NN + 127) / 128, 256, SMEM_TOT>>>(nullptr, nullptr, out, 1);
}